// round 6
// baseline (speedup 1.0000x reference)
#include <cuda_runtime.h>

// Problem shape (fixed by reference)
#define Bdim  128
#define Tdim  1024
#define Idim  64
#define Hdim  512
#define BBdim 128
#define Odim  2

#define NCTA 128   // one CTA per 4 hidden units; also CTA j <-> batch j for phys head
#define NTHR 512   // 16 warps

#define RS    68   // buffer row stride in floats (17 float4s -> conflict-free LDS.128)
#define PSTR  2176 // 128*17, partial-reduction block stride

// Cross-CTA state (persistent kernel; no allocations allowed)
__device__ float g_h[Bdim * Hdim];      // h_{t-1} / h_t
__device__ float g_hl[Bdim * Hdim];     // h_lstm at current step
__device__ float g_f[Bdim * BBdim];     // backbone activations
__device__ volatile unsigned g_arrive[NCTA];   // per-CTA barrier epoch slots
__device__ unsigned g_epoch_base;       // written ONLY after final barrier (safe base)

__device__ __forceinline__ float sigm(float v) { return 1.0f / (1.0f + expf(-v)); }

// Flag-array grid barrier. 128 CTAs, 1 CTA/SM, single wave => safe.
// Posting is concurrent (one slot per CTA); detection is 128 parallel polls.
// Epochs are monotonic across graph replays; the base is re-read each launch
// from g_epoch_base, which is only ever updated AFTER a full-grid barrier,
// so every CTA of a launch observes the same base (no start-skew race).
__device__ __forceinline__ void grid_sync(unsigned &expect, int j, int tid) {
    __syncthreads();                     // CTA-local completion of phase writes
    expect += 1u;
    if (tid == 0) {
        __threadfence();                 // release my CTA's global writes
        g_arrive[j] = expect;
    }
    if (tid < NCTA) {                    // 128 threads poll all slots in parallel
        unsigned v;
        do { v = g_arrive[tid]; } while ((int)(v - expect) < 0);
    }
    __syncthreads();
}

// 16 gate-FMAs against one broadcast activation, as 8 packed f32x2 FMAs.
// wrow points at 16 consecutive weights (gates 0..15) for one k, 16B-aligned.
__device__ __forceinline__ void fma16x2(unsigned long long acc[8],
                                        const float* wrow, float av) {
    unsigned long long av2;
    asm("mov.b64 %0, {%1, %1};" : "=l"(av2) : "r"(__float_as_uint(av)));
    #pragma unroll
    for (int g = 0; g < 4; ++g) {
        ulonglong2 w2 = *(const ulonglong2*)(wrow + g * 4);
        asm("fma.rn.f32x2 %0, %1, %2, %0;" : "+l"(acc[2*g])     : "l"(w2.x), "l"(av2));
        asm("fma.rn.f32x2 %0, %1, %2, %0;" : "+l"(acc[2*g + 1]) : "l"(w2.y), "l"(av2));
    }
}

__device__ __forceinline__ float pk_lo(unsigned long long p) {
    return __uint_as_float((unsigned)(p & 0xffffffffu));
}
__device__ __forceinline__ float pk_hi(unsigned long long p) {
    return __uint_as_float((unsigned)(p >> 32));
}

__global__ __launch_bounds__(NTHR, 1)
void cfc_kernel(const float* __restrict__ x,
                const float* __restrict__ lstm_Wi, const float* __restrict__ lstm_bi,
                const float* __restrict__ lstm_Wh,
                const float* __restrict__ bb_W,  const float* __restrict__ bb_b,
                const float* __restrict__ ff1_W, const float* __restrict__ ff1_b,
                const float* __restrict__ ff2_W, const float* __restrict__ ff2_b,
                const float* __restrict__ ta_W,  const float* __restrict__ ta_b,
                const float* __restrict__ tb_W,  const float* __restrict__ tb_b,
                const float* __restrict__ head_W, const float* __restrict__ head_b,
                float* __restrict__ out)
{
    extern __shared__ float sm[];
    float* wA2  = sm;                    // [576][16] gate weights, k-major layout
    float* wB   = wA2 + 576 * 16;        // [16][576] bb_W row block (row-major)
    float* wC2  = wB + 16 * 576;         // [128][16] ff1/ff2/ta/tb, k-major
    float* hW   = wC2 + 128 * 16;        // [2][512] head
    float* bA   = hW + 2 * 512;          // 16
    float* bB   = bA + 16;               // 16
    float* bC   = bB + 16;               // 16
    float* hb   = bC + 16;               // 16 (2 used)
    float* buf0 = hb + 16;               // [128][RS] streaming tile
    float* buf1 = buf0 + 128 * RS;       // [128][RS]

    const int tid = threadIdx.x;
    const int j   = blockIdx.x;          // owns hidden units 4j..4j+3; batch j for head
    const int b   = tid & 127;           // batch lane for GEMM phases
    const int qtr = tid >> 7;            // k-split 0..3 (uniform per warp)
    const int bb0 = (j >> 3) * 8;        // phase-B batch block
    const int jj0 = (j & 7) * 16;        // phase-B bb_W row block

    // Barrier epoch base: safe to read at any time before this CTA's first post
    // (only updated after a full-grid barrier at the end of a launch).
    unsigned expect = g_epoch_base;

    // ---- One-time: resident weights into smem ----
    // wA2[k*16 + q] = gate-row q at column k (x cols 0..63, then h cols)
    for (int idx = tid; idx < 576 * 16; idx += NTHR) {
        int k = idx >> 4, q = idx & 15;
        int grow = (q >> 2) * Hdim + 4 * j + (q & 3);   // gate g=q>>2, unit u=q&3
        wA2[idx] = (k < Idim) ? lstm_Wi[grow * Idim + k]
                              : lstm_Wh[grow * Hdim + (k - Idim)];
    }
    for (int idx = tid; idx < 16 * 576; idx += NTHR) {
        int r = idx / 576, k = idx - r * 576;
        wB[idx] = bb_W[(jj0 + r) * 576 + k];
    }
    // wC2[k*16 + r], r: 0..3 ff1, 4..7 ff2, 8..11 ta, 12..15 tb (unit u=r&3)
    for (int idx = tid; idx < 128 * 16; idx += NTHR) {
        int k = idx >> 4, r = idx & 15;
        const float* Wm = (r < 4) ? ff1_W : (r < 8) ? ff2_W : (r < 12) ? ta_W : tb_W;
        wC2[idx] = Wm[(4 * j + (r & 3)) * BBdim + k];
    }
    for (int idx = tid; idx < 2 * Hdim; idx += NTHR) hW[idx] = head_W[idx];
    if (tid < 16) {
        bA[tid] = lstm_bi[(tid >> 2) * Hdim + 4 * j + (tid & 3)];
        bB[tid] = bb_b[jj0 + tid];
        const float* bm = (tid < 4) ? ff1_b : (tid < 8) ? ff2_b : (tid < 12) ? ta_b : tb_b;
        bC[tid] = bm[4 * j + (tid & 3)];
    }
    if (tid < 2) hb[tid] = head_b[tid];
    __syncthreads();

    float cReg[4] = {0.f, 0.f, 0.f, 0.f};  // LSTM cell state, register-resident

    for (int t = 0; t < Tdim; ++t) {
        // ============ Phase A: z = [x_t,h] @ W.T, LSTM update ============
        unsigned long long acc2[8];
        #pragma unroll
        for (int p = 0; p < 8; p++) acc2[p] = 0ull;

        const int NCH = (t == 0) ? 1 : 9;   // h=0 at t=0: only the x chunk

        {   // stage chunk 0 (x_t: 128 batches x 64 cols) into buf0
            float4 st[4];
            #pragma unroll
            for (int r4 = 0; r4 < 4; r4++) {
                int idx4 = tid + NTHR * r4;
                int row = idx4 >> 4, c4 = idx4 & 15;
                st[r4] = *(const float4*)(x + (long)row * (Tdim * Idim) + t * Idim + c4 * 4);
            }
            #pragma unroll
            for (int r4 = 0; r4 < 4; r4++) {
                int idx4 = tid + NTHR * r4;
                int row = idx4 >> 4, c4 = idx4 & 15;
                *(float4*)(buf0 + row * RS + c4 * 4) = st[r4];
            }
        }
        __syncthreads();

        for (int c = 0; c < NCH; ++c) {
            float4 st[4];
            if (c + 1 < NCH) {               // prefetch next h chunk (h cols c*64..)
                #pragma unroll
                for (int r4 = 0; r4 < 4; r4++) {
                    int idx4 = tid + NTHR * r4;
                    int row = idx4 >> 4, c4 = idx4 & 15;
                    st[r4] = __ldcg((const float4*)(g_h + row * Hdim + c * 64 + c4 * 4));
                }
            }
            const float* base = ((c & 1) ? buf1 : buf0) + b * RS + qtr * 16;
            const float* wpc  = wA2 + (c * 64 + qtr * 16) * 16;
            #pragma unroll
            for (int g4 = 0; g4 < 4; ++g4) {
                float4 av = *(const float4*)(base + g4 * 4);
                const float* wk = wpc + g4 * 64;    // 4 k's x 16 gates
                fma16x2(acc2, wk +  0, av.x);
                fma16x2(acc2, wk + 16, av.y);
                fma16x2(acc2, wk + 32, av.z);
                fma16x2(acc2, wk + 48, av.w);
            }
            if (c + 1 < NCH) {
                float* nb = ((c + 1) & 1) ? buf1 : buf0;
                #pragma unroll
                for (int r4 = 0; r4 < 4; r4++) {
                    int idx4 = tid + NTHR * r4;
                    int row = idx4 >> 4, c4 = idx4 & 15;
                    *(float4*)(nb + row * RS + c4 * 4) = st[r4];
                }
            }
            __syncthreads();
        }

        // 4-way k-partial reduction (scalar stride-17 => conflict-free)
        if (qtr) {
            float* d = buf0 + (qtr - 1) * PSTR + b * 17;
            #pragma unroll
            for (int p = 0; p < 8; p++) {
                d[2 * p]     = pk_lo(acc2[p]);
                d[2 * p + 1] = pk_hi(acc2[p]);
            }
        }
        __syncthreads();
        if (!qtr) {
            float z[16];
            #pragma unroll
            for (int p = 0; p < 8; p++) {
                z[2 * p]     = pk_lo(acc2[p]);
                z[2 * p + 1] = pk_hi(acc2[p]);
            }
            #pragma unroll
            for (int q = 0; q < 16; q++)
                z[q] += buf0[b * 17 + q] + buf0[PSTR + b * 17 + q]
                      + buf0[2 * PSTR + b * 17 + q] + bA[q];
            float hl[4];
            #pragma unroll
            for (int u = 0; u < 4; u++) {
                // z rows: [0..3]=i_, [4..7]=ig, [8..11]=fg, [12..15]=og
                float cn = cReg[u] * sigm(z[8 + u] + 1.0f) + tanhf(z[u]) * sigm(z[4 + u]);
                cReg[u] = cn;
                hl[u] = tanhf(cn) * sigm(z[12 + u]);
            }
            *(float4*)(g_hl + b * Hdim + 4 * j) = make_float4(hl[0], hl[1], hl[2], hl[3]);
        }

        // phys output for step t-1 (g_h still holds h_{t-1}); CTA j handles batch j
        if (t > 0 && tid < 64) {
            int o = tid >> 5, l = tid & 31;
            float s = 0.f;
            for (int n = l; n < Hdim; n += 32)
                s += __ldcg(g_h + j * Hdim + n) * hW[o * Hdim + n];
            #pragma unroll
            for (int off = 16; off; off >>= 1) s += __shfl_down_sync(0xffffffffu, s, off);
            if (l == 0) out[((long)j * Tdim + (t - 1)) * Odim + o] = s + hb[o];
        }
        grid_sync(expect, j, tid);   // barrier 1: h_lstm complete

        // ============ Phase B: f = lecun_tanh([x_t,h_lstm] @ bbW.T + b) ============
        // CTA j computes f[bb0..bb0+7][jj0..jj0+15]; warp = (local batch, k-half)
        for (int idx4 = tid; idx4 < 8 * 144; idx4 += NTHR) {
            int row = idx4 / 144, c4 = idx4 - row * 144;
            int col = c4 * 4;
            float4 v;
            if (col < Idim)
                v = *(const float4*)(x + (long)(bb0 + row) * (Tdim * Idim) + t * Idim + col);
            else
                v = __ldcg((const float4*)(g_hl + (bb0 + row) * Hdim + col - Idim));
            *(float4*)(buf0 + row * 576 + col) = v;
        }
        __syncthreads();
        {
            int w  = tid >> 5, l = tid & 31;
            int lb = w >> 1, kh = w & 1;     // local batch 0..7, k-half 0/1
            float a[16];
            #pragma unroll
            for (int r = 0; r < 16; r++) a[r] = 0.f;
            const float* xr = buf0 + lb * 576 + kh * 288;
            const float* wb = wB + kh * 288;
            for (int it = 0; it < 9; ++it) {
                int kk = it * 32 + l;
                float v = xr[kk];
                #pragma unroll
                for (int r = 0; r < 16; r++) a[r] = fmaf(v, wb[r * 576 + kk], a[r]);
            }
            #pragma unroll
            for (int r = 0; r < 16; r++) {
                #pragma unroll
                for (int off = 16; off; off >>= 1)
                    a[r] += __shfl_down_sync(0xffffffffu, a[r], off);
            }
            if (l == 0) {
                #pragma unroll
                for (int r = 0; r < 16; r++) buf1[(lb * 2 + kh) * 16 + r] = a[r];
            }
        }
        __syncthreads();
        if (tid < 128) {    // distribute the tanh epilogue over 128 threads
            int lb = tid >> 4, r = tid & 15;
            float v = buf1[lb * 32 + r] + buf1[lb * 32 + 16 + r] + bB[r];
            g_f[(bb0 + lb) * BBdim + jj0 + r] = 1.7159f * tanhf(0.666f * v);
        }
        grid_sync(expect, j, tid);   // barrier 2: f complete

        // ============ Phase C: ff1/ff2/ta/tb, h_new ============
        #pragma unroll
        for (int r8 = 0; r8 < 8; ++r8) {     // stage full f (128x128) into buf0|buf1
            int idx4 = tid + NTHR * r8;      // 4096 float4
            int row = idx4 >> 5, c4 = idx4 & 31;
            float4 v = __ldcg((const float4*)(g_f + row * BBdim + c4 * 4));
            *(float4*)(((c4 < 16) ? buf0 : buf1) + row * RS + (c4 & 15) * 4) = v;
        }
        __syncthreads();
        unsigned long long c2[8];
        #pragma unroll
        for (int p = 0; p < 8; p++) c2[p] = 0ull;
        {
            const float* base = ((qtr >= 2) ? buf1 : buf0) + b * RS + (qtr & 1) * 32;
            const float* wpc  = wC2 + (qtr * 32) * 16;
            #pragma unroll
            for (int g4 = 0; g4 < 8; ++g4) {
                float4 av = *(const float4*)(base + g4 * 4);
                const float* wk = wpc + g4 * 64;
                fma16x2(c2, wk +  0, av.x);
                fma16x2(c2, wk + 16, av.y);
                fma16x2(c2, wk + 32, av.z);
                fma16x2(c2, wk + 48, av.w);
            }
        }
        __syncthreads();
        if (qtr) {
            float* d = buf0 + (qtr - 1) * PSTR + b * 17;
            #pragma unroll
            for (int p = 0; p < 8; p++) {
                d[2 * p]     = pk_lo(c2[p]);
                d[2 * p + 1] = pk_hi(c2[p]);
            }
        }
        __syncthreads();
        if (!qtr) {
            float z[16];
            #pragma unroll
            for (int p = 0; p < 8; p++) {
                z[2 * p]     = pk_lo(c2[p]);
                z[2 * p + 1] = pk_hi(c2[p]);
            }
            #pragma unroll
            for (int r = 0; r < 16; r++)
                z[r] += buf0[b * 17 + r] + buf0[PSTR + b * 17 + r]
                      + buf0[2 * PSTR + b * 17 + r] + bC[r];
            float hn[4];
            #pragma unroll
            for (int u = 0; u < 4; u++) {
                float f1 = tanhf(z[u]);                  // ff1
                float f2 = tanhf(z[4 + u]);              // ff2
                float ti = sigm(z[8 + u] + z[12 + u]);   // sigmoid(ta*1 + tb)
                hn[u] = f1 * (1.f - ti) + ti * f2;
            }
            *(float4*)(g_h + b * Hdim + 4 * j) = make_float4(hn[0], hn[1], hn[2], hn[3]);
        }
        grid_sync(expect, j, tid);   // barrier 3: h_t complete
    }

    // ---- Epilogue: phys for t = T-1, and last_h ----
    if (tid < 64) {
        int o = tid >> 5, l = tid & 31;
        float s = 0.f;
        for (int n = l; n < Hdim; n += 32)
            s += __ldcg(g_h + j * Hdim + n) * hW[o * Hdim + n];
        #pragma unroll
        for (int off = 16; off; off >>= 1) s += __shfl_down_sync(0xffffffffu, s, off);
        if (l == 0) out[((long)j * Tdim + (Tdim - 1)) * Odim + o] = s + hb[o];
    }
    float* out_lh = out + (long)Bdim * Tdim * Odim;
    for (int i4 = tid; i4 < Hdim / 4; i4 += NTHR) {
        float4 v = __ldcg((const float4*)(g_h + j * Hdim + i4 * 4));
        *(float4*)(out_lh + j * Hdim + i4 * 4) = v;
    }

    // Publish the new epoch base for the next launch. Safe: every CTA passed
    // the final grid barrier (their base reads happened at launch start), and
    // launches are serialized on the stream.
    if (j == 0 && tid == 0) {
        __threadfence();
        g_epoch_base = expect;
    }
}

extern "C" void kernel_launch(void* const* d_in, const int* in_sizes, int n_in,
                              void* d_out, int out_size) {
    (void)in_sizes; (void)n_in; (void)out_size;
    const int SMEM_BYTES = (576 * 16 + 16 * 576 + 128 * 16 + 2 * 512 + 64
                            + 2 * 128 * RS) * 4;
    cudaFuncSetAttribute(cfc_kernel, cudaFuncAttributeMaxDynamicSharedMemorySize, SMEM_BYTES);
    cfc_kernel<<<NCTA, NTHR, SMEM_BYTES>>>(
        (const float*)d_in[0],  (const float*)d_in[1],  (const float*)d_in[2],
        (const float*)d_in[3],  (const float*)d_in[4],  (const float*)d_in[5],
        (const float*)d_in[6],  (const float*)d_in[7],  (const float*)d_in[8],
        (const float*)d_in[9],  (const float*)d_in[10], (const float*)d_in[11],
        (const float*)d_in[12], (const float*)d_in[13], (const float*)d_in[14],
        (const float*)d_in[15], (float*)d_out);
}

// round 7
// speedup vs baseline: 1.5079x; 1.5079x over previous
#include <cuda_runtime.h>

// Problem shape (fixed by reference)
#define Bdim  128
#define Tdim  1024
#define Idim  64
#define Hdim  512
#define BBdim 128
#define Odim  2

#define NCTA 128   // one CTA per 4 hidden units; also CTA j <-> batch j for phys head
#define NTHR 512   // 16 warps

#define RS    68   // buffer row stride in floats (17 float4s -> conflict-free LDS.128)
#define PSTR  2176 // 128*17, partial-reduction block stride

// Cross-CTA state (persistent kernel; no allocations allowed)
__device__ float g_h[Bdim * Hdim];      // h_{t-1} / h_t
__device__ float g_hl[Bdim * Hdim];     // h_lstm at current step
__device__ float g_f[Bdim * BBdim];     // backbone activations
__device__ unsigned g_bar_count;
__device__ volatile unsigned g_bar_flag;

__device__ __forceinline__ float sigm(float v) { return 1.0f / (1.0f + expf(-v)); }

// R4's proven grid barrier. 128 CTAs, 1 CTA/SM, single wave => safe.
// The flag only advances when ALL CTAs arrive, so reading it at kernel start
// as the epoch base is race-free (no CTA can pass barrier 1 before every CTA
// has started and sampled the base).
__device__ __forceinline__ void grid_sync(unsigned &expect) {
    __syncthreads();
    if (threadIdx.x == 0) {
        expect += 1u;
        __threadfence();                         // release my phase's global writes
        if (atomicAdd(&g_bar_count, 1u) == NCTA - 1) {
            g_bar_count = 0;
            __threadfence();
            g_bar_flag = expect;
        } else {
            while (g_bar_flag != expect) { }
        }
    }
    __syncthreads();
}

// 16 gate-FMAs against one broadcast activation, as 8 packed f32x2 FMAs.
// wrow points at 16 consecutive weights (gates 0..15) for one k, 16B-aligned.
__device__ __forceinline__ void fma16x2(unsigned long long acc[8],
                                        const float* wrow, float av) {
    unsigned long long av2;
    asm("mov.b64 %0, {%1, %1};" : "=l"(av2) : "r"(__float_as_uint(av)));
    #pragma unroll
    for (int g = 0; g < 4; ++g) {
        ulonglong2 w2 = *(const ulonglong2*)(wrow + g * 4);
        asm("fma.rn.f32x2 %0, %1, %2, %0;" : "+l"(acc[2*g])     : "l"(w2.x), "l"(av2));
        asm("fma.rn.f32x2 %0, %1, %2, %0;" : "+l"(acc[2*g + 1]) : "l"(w2.y), "l"(av2));
    }
}

__device__ __forceinline__ float pk_lo(unsigned long long p) {
    return __uint_as_float((unsigned)(p & 0xffffffffu));
}
__device__ __forceinline__ float pk_hi(unsigned long long p) {
    return __uint_as_float((unsigned)(p >> 32));
}

__global__ __launch_bounds__(NTHR, 1)
void cfc_kernel(const float* __restrict__ x,
                const float* __restrict__ lstm_Wi, const float* __restrict__ lstm_bi,
                const float* __restrict__ lstm_Wh,
                const float* __restrict__ bb_W,  const float* __restrict__ bb_b,
                const float* __restrict__ ff1_W, const float* __restrict__ ff1_b,
                const float* __restrict__ ff2_W, const float* __restrict__ ff2_b,
                const float* __restrict__ ta_W,  const float* __restrict__ ta_b,
                const float* __restrict__ tb_W,  const float* __restrict__ tb_b,
                const float* __restrict__ head_W, const float* __restrict__ head_b,
                float* __restrict__ out)
{
    extern __shared__ float sm[];
    float* wA2  = sm;                    // [576][16] gate weights, k-major layout
    float* wB   = wA2 + 576 * 16;        // [16][576] bb_W row block (row-major)
    float* wC2  = wB + 16 * 576;         // [128][16] ff1/ff2/ta/tb, k-major
    float* hW   = wC2 + 128 * 16;        // [2][512] head
    float* bA   = hW + 2 * 512;          // 16
    float* bB   = bA + 16;               // 16
    float* bC   = bB + 16;               // 16
    float* hb   = bC + 16;               // 16 (2 used)
    float* buf0 = hb + 16;               // [128][RS] streaming tile
    float* buf1 = buf0 + 128 * RS;       // [128][RS]

    const int tid = threadIdx.x;
    const int j   = blockIdx.x;          // owns hidden units 4j..4j+3; batch j for head
    const int b   = tid & 127;           // batch lane for GEMM phases
    const int qtr = tid >> 7;            // k-split 0..3 (uniform per warp)
    const int bb0 = (j >> 3) * 8;        // phase-B batch block
    const int jj0 = (j & 7) * 16;        // phase-B bb_W row block

    // ---- One-time: resident weights into smem ----
    // wA2[k*16 + q] = gate-row q at column k (x cols 0..63, then h cols)
    for (int idx = tid; idx < 576 * 16; idx += NTHR) {
        int k = idx >> 4, q = idx & 15;
        int grow = (q >> 2) * Hdim + 4 * j + (q & 3);   // gate g=q>>2, unit u=q&3
        wA2[idx] = (k < Idim) ? lstm_Wi[grow * Idim + k]
                              : lstm_Wh[grow * Hdim + (k - Idim)];
    }
    for (int idx = tid; idx < 16 * 576; idx += NTHR) {
        int r = idx / 576, k = idx - r * 576;
        wB[idx] = bb_W[(jj0 + r) * 576 + k];
    }
    // wC2[k*16 + r], r: 0..3 ff1, 4..7 ff2, 8..11 ta, 12..15 tb (unit u=r&3)
    for (int idx = tid; idx < 128 * 16; idx += NTHR) {
        int k = idx >> 4, r = idx & 15;
        const float* Wm = (r < 4) ? ff1_W : (r < 8) ? ff2_W : (r < 12) ? ta_W : tb_W;
        wC2[idx] = Wm[(4 * j + (r & 3)) * BBdim + k];
    }
    for (int idx = tid; idx < 2 * Hdim; idx += NTHR) hW[idx] = head_W[idx];
    if (tid < 16) {
        bA[tid] = lstm_bi[(tid >> 2) * Hdim + 4 * j + (tid & 3)];
        bB[tid] = bb_b[jj0 + tid];
        const float* bm = (tid < 4) ? ff1_b : (tid < 8) ? ff2_b : (tid < 12) ? ta_b : tb_b;
        bC[tid] = bm[4 * j + (tid & 3)];
    }
    if (tid < 2) hb[tid] = head_b[tid];
    __syncthreads();

    unsigned expect = 0;
    if (tid == 0) expect = g_bar_flag;   // race-free epoch base (see grid_sync)

    float cReg[4] = {0.f, 0.f, 0.f, 0.f};  // LSTM cell state, register-resident

    for (int t = 0; t < Tdim; ++t) {
        // ============ Phase A: z = [x_t,h] @ W.T, LSTM update ============
        unsigned long long acc2[8];
        #pragma unroll
        for (int p = 0; p < 8; p++) acc2[p] = 0ull;

        const int NCH = (t == 0) ? 1 : 9;   // h=0 at t=0: only the x chunk

        {   // stage chunk 0 (x_t: 128 batches x 64 cols) into buf0
            float4 st[4];
            #pragma unroll
            for (int r4 = 0; r4 < 4; r4++) {
                int idx4 = tid + NTHR * r4;
                int row = idx4 >> 4, c4 = idx4 & 15;
                st[r4] = *(const float4*)(x + (long)row * (Tdim * Idim) + t * Idim + c4 * 4);
            }
            #pragma unroll
            for (int r4 = 0; r4 < 4; r4++) {
                int idx4 = tid + NTHR * r4;
                int row = idx4 >> 4, c4 = idx4 & 15;
                *(float4*)(buf0 + row * RS + c4 * 4) = st[r4];
            }
        }
        __syncthreads();

        for (int c = 0; c < NCH; ++c) {
            float4 st[4];
            if (c + 1 < NCH) {               // prefetch next h chunk (h cols c*64..)
                #pragma unroll
                for (int r4 = 0; r4 < 4; r4++) {
                    int idx4 = tid + NTHR * r4;
                    int row = idx4 >> 4, c4 = idx4 & 15;
                    st[r4] = __ldcg((const float4*)(g_h + row * Hdim + c * 64 + c4 * 4));
                }
            }
            const float* base = ((c & 1) ? buf1 : buf0) + b * RS + qtr * 16;
            const float* wpc  = wA2 + (c * 64 + qtr * 16) * 16;
            #pragma unroll
            for (int g4 = 0; g4 < 4; ++g4) {
                float4 av = *(const float4*)(base + g4 * 4);
                const float* wk = wpc + g4 * 64;    // 4 k's x 16 gates
                fma16x2(acc2, wk +  0, av.x);
                fma16x2(acc2, wk + 16, av.y);
                fma16x2(acc2, wk + 32, av.z);
                fma16x2(acc2, wk + 48, av.w);
            }
            if (c + 1 < NCH) {
                float* nb = ((c + 1) & 1) ? buf1 : buf0;
                #pragma unroll
                for (int r4 = 0; r4 < 4; r4++) {
                    int idx4 = tid + NTHR * r4;
                    int row = idx4 >> 4, c4 = idx4 & 15;
                    *(float4*)(nb + row * RS + c4 * 4) = st[r4];
                }
            }
            __syncthreads();
        }

        // 4-way k-partial reduction (scalar stride-17 => conflict-free)
        if (qtr) {
            float* d = buf0 + (qtr - 1) * PSTR + b * 17;
            #pragma unroll
            for (int p = 0; p < 8; p++) {
                d[2 * p]     = pk_lo(acc2[p]);
                d[2 * p + 1] = pk_hi(acc2[p]);
            }
        }
        __syncthreads();
        if (!qtr) {
            float z[16];
            #pragma unroll
            for (int p = 0; p < 8; p++) {
                z[2 * p]     = pk_lo(acc2[p]);
                z[2 * p + 1] = pk_hi(acc2[p]);
            }
            #pragma unroll
            for (int q = 0; q < 16; q++)
                z[q] += buf0[b * 17 + q] + buf0[PSTR + b * 17 + q]
                      + buf0[2 * PSTR + b * 17 + q] + bA[q];
            float hl[4];
            #pragma unroll
            for (int u = 0; u < 4; u++) {
                // z rows: [0..3]=i_, [4..7]=ig, [8..11]=fg, [12..15]=og
                float cn = cReg[u] * sigm(z[8 + u] + 1.0f) + tanhf(z[u]) * sigm(z[4 + u]);
                cReg[u] = cn;
                hl[u] = tanhf(cn) * sigm(z[12 + u]);
            }
            *(float4*)(g_hl + b * Hdim + 4 * j) = make_float4(hl[0], hl[1], hl[2], hl[3]);
        }

        // phys output for step t-1 (g_h still holds h_{t-1}); CTA j handles batch j
        if (t > 0 && tid < 64) {
            int o = tid >> 5, l = tid & 31;
            float s = 0.f;
            for (int n = l; n < Hdim; n += 32)
                s += __ldcg(g_h + j * Hdim + n) * hW[o * Hdim + n];
            #pragma unroll
            for (int off = 16; off; off >>= 1) s += __shfl_down_sync(0xffffffffu, s, off);
            if (l == 0) out[((long)j * Tdim + (t - 1)) * Odim + o] = s + hb[o];
        }
        grid_sync(expect);   // barrier 1: h_lstm complete

        // ============ Phase B: f = lecun_tanh([x_t,h_lstm] @ bbW.T + b) ============
        // CTA j computes f[bb0..bb0+7][jj0..jj0+15]; warp = (local batch, k-half)
        for (int idx4 = tid; idx4 < 8 * 144; idx4 += NTHR) {
            int row = idx4 / 144, c4 = idx4 - row * 144;
            int col = c4 * 4;
            float4 v;
            if (col < Idim)
                v = *(const float4*)(x + (long)(bb0 + row) * (Tdim * Idim) + t * Idim + col);
            else
                v = __ldcg((const float4*)(g_hl + (bb0 + row) * Hdim + col - Idim));
            *(float4*)(buf0 + row * 576 + col) = v;
        }
        __syncthreads();
        {
            int w  = tid >> 5, l = tid & 31;
            int lb = w >> 1, kh = w & 1;     // local batch 0..7, k-half 0/1
            float a[16];
            #pragma unroll
            for (int r = 0; r < 16; r++) a[r] = 0.f;
            const float* xr = buf0 + lb * 576 + kh * 288;
            const float* wb = wB + kh * 288;
            for (int it = 0; it < 9; ++it) {
                int kk = it * 32 + l;
                float v = xr[kk];
                #pragma unroll
                for (int r = 0; r < 16; r++) a[r] = fmaf(v, wb[r * 576 + kk], a[r]);
            }
            #pragma unroll
            for (int r = 0; r < 16; r++) {
                #pragma unroll
                for (int off = 16; off; off >>= 1)
                    a[r] += __shfl_down_sync(0xffffffffu, a[r], off);
            }
            if (l == 0) {
                #pragma unroll
                for (int r = 0; r < 16; r++) buf1[(lb * 2 + kh) * 16 + r] = a[r];
            }
        }
        __syncthreads();
        if (tid < 128) {    // distribute the tanh epilogue over 128 threads
            int lb = tid >> 4, r = tid & 15;
            float v = buf1[lb * 32 + r] + buf1[lb * 32 + 16 + r] + bB[r];
            g_f[(bb0 + lb) * BBdim + jj0 + r] = 1.7159f * tanhf(0.666f * v);
        }
        grid_sync(expect);   // barrier 2: f complete

        // ============ Phase C: ff1/ff2/ta/tb, h_new ============
        #pragma unroll
        for (int r8 = 0; r8 < 8; ++r8) {     // stage full f (128x128) into buf0|buf1
            int idx4 = tid + NTHR * r8;      // 4096 float4
            int row = idx4 >> 5, c4 = idx4 & 31;
            float4 v = __ldcg((const float4*)(g_f + row * BBdim + c4 * 4));
            *(float4*)(((c4 < 16) ? buf0 : buf1) + row * RS + (c4 & 15) * 4) = v;
        }
        __syncthreads();
        unsigned long long c2[8];
        #pragma unroll
        for (int p = 0; p < 8; p++) c2[p] = 0ull;
        {
            const float* base = ((qtr >= 2) ? buf1 : buf0) + b * RS + (qtr & 1) * 32;
            const float* wpc  = wC2 + (qtr * 32) * 16;
            #pragma unroll
            for (int g4 = 0; g4 < 8; ++g4) {
                float4 av = *(const float4*)(base + g4 * 4);
                const float* wk = wpc + g4 * 64;
                fma16x2(c2, wk +  0, av.x);
                fma16x2(c2, wk + 16, av.y);
                fma16x2(c2, wk + 32, av.z);
                fma16x2(c2, wk + 48, av.w);
            }
        }
        __syncthreads();
        if (qtr) {
            float* d = buf0 + (qtr - 1) * PSTR + b * 17;
            #pragma unroll
            for (int p = 0; p < 8; p++) {
                d[2 * p]     = pk_lo(c2[p]);
                d[2 * p + 1] = pk_hi(c2[p]);
            }
        }
        __syncthreads();
        if (!qtr) {
            float z[16];
            #pragma unroll
            for (int p = 0; p < 8; p++) {
                z[2 * p]     = pk_lo(c2[p]);
                z[2 * p + 1] = pk_hi(c2[p]);
            }
            #pragma unroll
            for (int r = 0; r < 16; r++)
                z[r] += buf0[b * 17 + r] + buf0[PSTR + b * 17 + r]
                      + buf0[2 * PSTR + b * 17 + r] + bC[r];
            float hn[4];
            #pragma unroll
            for (int u = 0; u < 4; u++) {
                float f1 = tanhf(z[u]);                  // ff1
                float f2 = tanhf(z[4 + u]);              // ff2
                float ti = sigm(z[8 + u] + z[12 + u]);   // sigmoid(ta*1 + tb)
                hn[u] = f1 * (1.f - ti) + ti * f2;
            }
            *(float4*)(g_h + b * Hdim + 4 * j) = make_float4(hn[0], hn[1], hn[2], hn[3]);
        }
        grid_sync(expect);   // barrier 3: h_t complete
    }

    // ---- Epilogue: phys for t = T-1, and last_h ----
    if (tid < 64) {
        int o = tid >> 5, l = tid & 31;
        float s = 0.f;
        for (int n = l; n < Hdim; n += 32)
            s += __ldcg(g_h + j * Hdim + n) * hW[o * Hdim + n];
        #pragma unroll
        for (int off = 16; off; off >>= 1) s += __shfl_down_sync(0xffffffffu, s, off);
        if (l == 0) out[((long)j * Tdim + (Tdim - 1)) * Odim + o] = s + hb[o];
    }
    float* out_lh = out + (long)Bdim * Tdim * Odim;
    for (int i4 = tid; i4 < Hdim / 4; i4 += NTHR) {
        float4 v = __ldcg((const float4*)(g_h + j * Hdim + i4 * 4));
        *(float4*)(out_lh + j * Hdim + i4 * 4) = v;
    }
}

extern "C" void kernel_launch(void* const* d_in, const int* in_sizes, int n_in,
                              void* d_out, int out_size) {
    (void)in_sizes; (void)n_in; (void)out_size;
    const int SMEM_BYTES = (576 * 16 + 16 * 576 + 128 * 16 + 2 * 512 + 64
                            + 2 * 128 * RS) * 4;
    cudaFuncSetAttribute(cfc_kernel, cudaFuncAttributeMaxDynamicSharedMemorySize, SMEM_BYTES);
    cfc_kernel<<<NCTA, NTHR, SMEM_BYTES>>>(
        (const float*)d_in[0],  (const float*)d_in[1],  (const float*)d_in[2],
        (const float*)d_in[3],  (const float*)d_in[4],  (const float*)d_in[5],
        (const float*)d_in[6],  (const float*)d_in[7],  (const float*)d_in[8],
        (const float*)d_in[9],  (const float*)d_in[10], (const float*)d_in[11],
        (const float*)d_in[12], (const float*)d_in[13], (const float*)d_in[14],
        (const float*)d_in[15], (float*)d_out);
}

// round 8
// speedup vs baseline: 1.5984x; 1.0600x over previous
#include <cuda_runtime.h>

// Problem shape (fixed by reference)
#define Bdim  128
#define Tdim  1024
#define Idim  64
#define Hdim  512
#define BBdim 128
#define Odim  2

#define NCTA 128   // one CTA per 4 hidden units; also CTA j <-> batch j for phys head
#define NTHR 512   // 16 warps

#define RS    68   // buffer row stride in floats (17 float4s -> conflict-free LDS.128)
#define PSTR  2176 // 128*17, partial-reduction block stride

// Cross-CTA state (persistent kernel; no allocations allowed)
__device__ float g_h[Bdim * Hdim];      // h_{t-1} / h_t
__device__ float g_hl[Bdim * Hdim];     // h_lstm at current step
__device__ float g_f[Bdim * BBdim];     // backbone activations
__device__ unsigned g_bar_count;
__device__ volatile unsigned g_bar_flag;

__device__ __forceinline__ float sigm(float v) { return 1.0f / (1.0f + expf(-v)); }

// R7's proven atomic barrier, split into arrive / wait so independent work can
// fill the wait window. Flag only advances when ALL CTAs arrive, so reading it
// at kernel start as the epoch base is race-free.
__device__ __forceinline__ void bar_arrive(unsigned &expect) {
    __syncthreads();                     // CTA-local completion of phase writes
    expect += 1u;                        // all threads track (only tid 0's used)
    if (threadIdx.x == 0) {
        __threadfence();                 // release my phase's global writes
        if (atomicAdd(&g_bar_count, 1u) == NCTA - 1) {
            g_bar_count = 0;
            __threadfence();
            g_bar_flag = expect;
        }
    }
}
__device__ __forceinline__ void bar_wait(unsigned expect) {
    if (threadIdx.x == 0) {
        while (g_bar_flag != expect) { }
    }
    __syncthreads();
}

// 16 gate-FMAs against one broadcast activation, as 8 packed f32x2 FMAs.
__device__ __forceinline__ void fma16x2(unsigned long long acc[8],
                                        const float* wrow, float av) {
    unsigned long long av2;
    asm("mov.b64 %0, {%1, %1};" : "=l"(av2) : "r"(__float_as_uint(av)));
    #pragma unroll
    for (int g = 0; g < 4; ++g) {
        ulonglong2 w2 = *(const ulonglong2*)(wrow + g * 4);
        asm("fma.rn.f32x2 %0, %1, %2, %0;" : "+l"(acc[2*g])     : "l"(w2.x), "l"(av2));
        asm("fma.rn.f32x2 %0, %1, %2, %0;" : "+l"(acc[2*g + 1]) : "l"(w2.y), "l"(av2));
    }
}

// One 4-k slab of the gate GEMM: g4 in [LO, HI)
template <int LO, int HI>
__device__ __forceinline__ void gemmA_part(unsigned long long acc2[8],
                                           const float* base, const float* wpc) {
    #pragma unroll
    for (int g4 = LO; g4 < HI; ++g4) {
        float4 av = *(const float4*)(base + g4 * 4);
        const float* wk = wpc + g4 * 64;    // 4 k's x 16 gates
        fma16x2(acc2, wk +  0, av.x);
        fma16x2(acc2, wk + 16, av.y);
        fma16x2(acc2, wk + 32, av.z);
        fma16x2(acc2, wk + 48, av.w);
    }
}

__device__ __forceinline__ float pk_lo(unsigned long long p) {
    return __uint_as_float((unsigned)(p & 0xffffffffu));
}
__device__ __forceinline__ float pk_hi(unsigned long long p) {
    return __uint_as_float((unsigned)(p >> 32));
}

__global__ __launch_bounds__(NTHR, 1)
void cfc_kernel(const float* __restrict__ x,
                const float* __restrict__ lstm_Wi, const float* __restrict__ lstm_bi,
                const float* __restrict__ lstm_Wh,
                const float* __restrict__ bb_W,  const float* __restrict__ bb_b,
                const float* __restrict__ ff1_W, const float* __restrict__ ff1_b,
                const float* __restrict__ ff2_W, const float* __restrict__ ff2_b,
                const float* __restrict__ ta_W,  const float* __restrict__ ta_b,
                const float* __restrict__ tb_W,  const float* __restrict__ tb_b,
                const float* __restrict__ head_W, const float* __restrict__ head_b,
                float* __restrict__ out)
{
    extern __shared__ float sm[];
    float* wA2  = sm;                    // [576][16] gate weights, k-major layout
    float* wB   = wA2 + 576 * 16;        // [16][576] bb_W row block (row-major)
    float* wC2  = wB + 16 * 576;         // [128][16] ff1/ff2/ta/tb, k-major
    float* hW   = wC2 + 128 * 16;        // [2][512] head
    float* bA   = hW + 2 * 512;          // 16
    float* bB   = bA + 16;               // 16
    float* bC   = bB + 16;               // 16
    float* hb   = bC + 16;               // 16 (2 used)
    float* buf0 = hb + 16;               // [128][RS] streaming tile
    float* buf1 = buf0 + 128 * RS;       // [128][RS]

    const int tid = threadIdx.x;
    const int j   = blockIdx.x;          // owns hidden units 4j..4j+3; batch j for head
    const int b   = tid & 127;           // batch lane for GEMM phases
    const int qtr = tid >> 7;            // k-split 0..3 (uniform per warp)
    const int bb0 = (j >> 3) * 8;        // phase-B batch block
    const int jj0 = (j & 7) * 16;        // phase-B bb_W row block

    // ---- One-time: resident weights into smem ----
    for (int idx = tid; idx < 576 * 16; idx += NTHR) {
        int k = idx >> 4, q = idx & 15;
        int grow = (q >> 2) * Hdim + 4 * j + (q & 3);   // gate g=q>>2, unit u=q&3
        wA2[idx] = (k < Idim) ? lstm_Wi[grow * Idim + k]
                              : lstm_Wh[grow * Hdim + (k - Idim)];
    }
    for (int idx = tid; idx < 16 * 576; idx += NTHR) {
        int r = idx / 576, k = idx - r * 576;
        wB[idx] = bb_W[(jj0 + r) * 576 + k];
    }
    for (int idx = tid; idx < 128 * 16; idx += NTHR) {
        int k = idx >> 4, r = idx & 15;
        const float* Wm = (r < 4) ? ff1_W : (r < 8) ? ff2_W : (r < 12) ? ta_W : tb_W;
        wC2[idx] = Wm[(4 * j + (r & 3)) * BBdim + k];
    }
    for (int idx = tid; idx < 2 * Hdim; idx += NTHR) hW[idx] = head_W[idx];
    if (tid < 16) {
        bA[tid] = lstm_bi[(tid >> 2) * Hdim + 4 * j + (tid & 3)];
        bB[tid] = bb_b[jj0 + tid];
        const float* bm = (tid < 4) ? ff1_b : (tid < 8) ? ff2_b : (tid < 12) ? ta_b : tb_b;
        bC[tid] = bm[4 * j + (tid & 3)];
    }
    if (tid < 2) hb[tid] = head_b[tid];
    __syncthreads();

    unsigned expect = 0;
    if (tid == 0) expect = g_bar_flag;   // race-free epoch base

    float cReg[4] = {0.f, 0.f, 0.f, 0.f};  // LSTM cell state, register-resident

    for (int t = 0; t < Tdim; ++t) {
        // ============ Phase A: z = [x_t,h] @ W.T, LSTM update ============
        unsigned long long acc2[8];
        #pragma unroll
        for (int p = 0; p < 8; p++) acc2[p] = 0ull;

        // --- bar3(t-1) overlap window: stage x chunk 0, compute its 1st half ---
        {
            float4 st[4];
            #pragma unroll
            for (int r4 = 0; r4 < 4; r4++) {
                int idx4 = tid + NTHR * r4;
                int row = idx4 >> 4, c4 = idx4 & 15;
                st[r4] = *(const float4*)(x + (long)row * (Tdim * Idim) + t * Idim + c4 * 4);
            }
            #pragma unroll
            for (int r4 = 0; r4 < 4; r4++) {
                int idx4 = tid + NTHR * r4;
                int row = idx4 >> 4, c4 = idx4 & 15;
                *(float4*)(buf0 + row * RS + c4 * 4) = st[r4];
            }
        }
        __syncthreads();
        gemmA_part<0, 2>(acc2, buf0 + b * RS + qtr * 16, wA2 + (qtr * 16) * 16);

        bar_wait(expect);    // bar3(t-1): h_{t-1} ready (no-op at t=0)

        if (t > 0) {
            float4 st[4];
            // prefetch h chunk 1 (g_h cols 0..63) while finishing chunk 0
            #pragma unroll
            for (int r4 = 0; r4 < 4; r4++) {
                int idx4 = tid + NTHR * r4;
                int row = idx4 >> 4, c4 = idx4 & 15;
                st[r4] = __ldcg((const float4*)(g_h + row * Hdim + c4 * 4));
            }
            gemmA_part<2, 4>(acc2, buf0 + b * RS + qtr * 16, wA2 + (qtr * 16) * 16);
            #pragma unroll
            for (int r4 = 0; r4 < 4; r4++) {
                int idx4 = tid + NTHR * r4;
                int row = idx4 >> 4, c4 = idx4 & 15;
                *(float4*)(buf1 + row * RS + c4 * 4) = st[r4];
            }
            __syncthreads();

            for (int c = 1; c < 9; ++c) {
                float4 st2[4];
                if (c < 8) {             // prefetch next h chunk (g_h cols c*64..)
                    #pragma unroll
                    for (int r4 = 0; r4 < 4; r4++) {
                        int idx4 = tid + NTHR * r4;
                        int row = idx4 >> 4, c4 = idx4 & 15;
                        st2[r4] = __ldcg((const float4*)(g_h + row * Hdim + c * 64 + c4 * 4));
                    }
                }
                gemmA_part<0, 4>(acc2,
                                 ((c & 1) ? buf1 : buf0) + b * RS + qtr * 16,
                                 wA2 + (c * 64 + qtr * 16) * 16);
                if (c < 8) {
                    float* nb = ((c + 1) & 1) ? buf1 : buf0;
                    #pragma unroll
                    for (int r4 = 0; r4 < 4; r4++) {
                        int idx4 = tid + NTHR * r4;
                        int row = idx4 >> 4, c4 = idx4 & 15;
                        *(float4*)(nb + row * RS + c4 * 4) = st2[r4];
                    }
                }
                __syncthreads();
            }
        } else {
            gemmA_part<2, 4>(acc2, buf0 + b * RS + qtr * 16, wA2 + (qtr * 16) * 16);
            __syncthreads();             // protect buf0 before reduction writes
        }

        // 4-way k-partial reduction (scalar stride-17 => conflict-free)
        if (qtr) {
            float* d = buf0 + (qtr - 1) * PSTR + b * 17;
            #pragma unroll
            for (int p = 0; p < 8; p++) {
                d[2 * p]     = pk_lo(acc2[p]);
                d[2 * p + 1] = pk_hi(acc2[p]);
            }
        }
        __syncthreads();
        if (!qtr) {
            float z[16];
            #pragma unroll
            for (int p = 0; p < 8; p++) {
                z[2 * p]     = pk_lo(acc2[p]);
                z[2 * p + 1] = pk_hi(acc2[p]);
            }
            #pragma unroll
            for (int q = 0; q < 16; q++)
                z[q] += buf0[b * 17 + q] + buf0[PSTR + b * 17 + q]
                      + buf0[2 * PSTR + b * 17 + q] + bA[q];
            float hl[4];
            #pragma unroll
            for (int u = 0; u < 4; u++) {
                // z rows: [0..3]=i_, [4..7]=ig, [8..11]=fg, [12..15]=og
                float cn = cReg[u] * sigm(z[8 + u] + 1.0f) + tanhf(z[u]) * sigm(z[4 + u]);
                cReg[u] = cn;
                hl[u] = tanhf(cn) * sigm(z[12 + u]);
            }
            *(float4*)(g_hl + b * Hdim + 4 * j) = make_float4(hl[0], hl[1], hl[2], hl[3]);
        }

        bar_arrive(expect);  // bar1: h_lstm posted

        // --- bar1 overlap window: phys head (t-1) + Phase-B x staging ---
        // g_h is stable here: no CTA can pass bar2 until this CTA arrives there.
        if (t > 0 && tid < 64) {
            int o = tid >> 5, l = tid & 31;
            float s = 0.f;
            for (int n = l; n < Hdim; n += 32)
                s += __ldcg(g_h + j * Hdim + n) * hW[o * Hdim + n];
            #pragma unroll
            for (int off = 16; off; off >>= 1) s += __shfl_down_sync(0xffffffffu, s, off);
            if (l == 0) out[((long)j * Tdim + (t - 1)) * Odim + o] = s + hb[o];
        }
        if (tid >= 128 && tid < 256) {   // B rows' x columns (no h_lstm dependency)
            int idx = tid - 128;
            int row = idx >> 4, col = (idx & 15) * 4;
            *(float4*)(buf0 + row * 576 + col) =
                *(const float4*)(x + (long)(bb0 + row) * (Tdim * Idim) + t * Idim + col);
        }

        bar_wait(expect);    // bar1: h_lstm ready

        // ============ Phase B: f = lecun_tanh([x_t,h_lstm] @ bbW.T + b) ============
        #pragma unroll
        for (int r2 = 0; r2 < 2; ++r2) {     // stage h_lstm columns (rows 8 x cols 512)
            int idx4 = tid + NTHR * r2;      // 1024 float4
            int row = idx4 >> 7, c4 = idx4 & 127;
            int col = 64 + c4 * 4;
            *(float4*)(buf0 + row * 576 + col) =
                __ldcg((const float4*)(g_hl + (bb0 + row) * Hdim + col - 64));
        }
        __syncthreads();
        {
            int w  = tid >> 5, l = tid & 31;
            int lb = w >> 1, kh = w & 1;     // local batch 0..7, k-half 0/1
            float a[16];
            #pragma unroll
            for (int r = 0; r < 16; r++) a[r] = 0.f;
            const float* xr = buf0 + lb * 576 + kh * 288;
            const float* wb = wB + kh * 288;
            for (int it = 0; it < 9; ++it) {
                int kk = it * 32 + l;
                float v = xr[kk];
                #pragma unroll
                for (int r = 0; r < 16; r++) a[r] = fmaf(v, wb[r * 576 + kk], a[r]);
            }
            #pragma unroll
            for (int r = 0; r < 16; r++) {
                #pragma unroll
                for (int off = 16; off; off >>= 1)
                    a[r] += __shfl_down_sync(0xffffffffu, a[r], off);
            }
            if (l == 0) {
                #pragma unroll
                for (int r = 0; r < 16; r++) buf1[(lb * 2 + kh) * 16 + r] = a[r];
            }
        }
        __syncthreads();
        if (tid < 128) {    // distribute the tanh epilogue over 128 threads
            int lb = tid >> 4, r = tid & 15;
            float v = buf1[lb * 32 + r] + buf1[lb * 32 + 16 + r] + bB[r];
            g_f[(bb0 + lb) * BBdim + jj0 + r] = 1.7159f * tanhf(0.666f * v);
        }

        bar_arrive(expect);  // bar2: f posted
        bar_wait(expect);    // bar2: f ready (no independent work exists here)

        // ============ Phase C: ff1/ff2/ta/tb, h_new ============
        #pragma unroll
        for (int r8 = 0; r8 < 8; ++r8) {     // stage full f (128x128) into buf0|buf1
            int idx4 = tid + NTHR * r8;      // 4096 float4
            int row = idx4 >> 5, c4 = idx4 & 31;
            float4 v = __ldcg((const float4*)(g_f + row * BBdim + c4 * 4));
            *(float4*)(((c4 < 16) ? buf0 : buf1) + row * RS + (c4 & 15) * 4) = v;
        }
        __syncthreads();
        unsigned long long c2[8];
        #pragma unroll
        for (int p = 0; p < 8; p++) c2[p] = 0ull;
        {
            const float* base = ((qtr >= 2) ? buf1 : buf0) + b * RS + (qtr & 1) * 32;
            const float* wpc  = wC2 + (qtr * 32) * 16;
            #pragma unroll
            for (int g4 = 0; g4 < 8; ++g4) {
                float4 av = *(const float4*)(base + g4 * 4);
                const float* wk = wpc + g4 * 64;
                fma16x2(c2, wk +  0, av.x);
                fma16x2(c2, wk + 16, av.y);
                fma16x2(c2, wk + 32, av.z);
                fma16x2(c2, wk + 48, av.w);
            }
        }
        __syncthreads();
        if (qtr) {
            float* d = buf0 + (qtr - 1) * PSTR + b * 17;
            #pragma unroll
            for (int p = 0; p < 8; p++) {
                d[2 * p]     = pk_lo(c2[p]);
                d[2 * p + 1] = pk_hi(c2[p]);
            }
        }
        __syncthreads();
        if (!qtr) {
            float z[16];
            #pragma unroll
            for (int p = 0; p < 8; p++) {
                z[2 * p]     = pk_lo(c2[p]);
                z[2 * p + 1] = pk_hi(c2[p]);
            }
            #pragma unroll
            for (int r = 0; r < 16; r++)
                z[r] += buf0[b * 17 + r] + buf0[PSTR + b * 17 + r]
                      + buf0[2 * PSTR + b * 17 + r] + bC[r];
            float hn[4];
            #pragma unroll
            for (int u = 0; u < 4; u++) {
                float f1 = tanhf(z[u]);                  // ff1
                float f2 = tanhf(z[4 + u]);              // ff2
                float ti = sigm(z[8 + u] + z[12 + u]);   // sigmoid(ta*1 + tb)
                hn[u] = f1 * (1.f - ti) + ti * f2;
            }
            *(float4*)(g_h + b * Hdim + 4 * j) = make_float4(hn[0], hn[1], hn[2], hn[3]);
        }

        bar_arrive(expect);  // bar3: h_t posted (waited at top of next iteration)
    }

    bar_wait(expect);        // final bar3: h_{T-1} ready everywhere

    // ---- Epilogue: phys for t = T-1, and last_h ----
    if (tid < 64) {
        int o = tid >> 5, l = tid & 31;
        float s = 0.f;
        for (int n = l; n < Hdim; n += 32)
            s += __ldcg(g_h + j * Hdim + n) * hW[o * Hdim + n];
        #pragma unroll
        for (int off = 16; off; off >>= 1) s += __shfl_down_sync(0xffffffffu, s, off);
        if (l == 0) out[((long)j * Tdim + (Tdim - 1)) * Odim + o] = s + hb[o];
    }
    float* out_lh = out + (long)Bdim * Tdim * Odim;
    for (int i4 = tid; i4 < Hdim / 4; i4 += NTHR) {
        float4 v = __ldcg((const float4*)(g_h + j * Hdim + i4 * 4));
        *(float4*)(out_lh + j * Hdim + i4 * 4) = v;
    }
}

extern "C" void kernel_launch(void* const* d_in, const int* in_sizes, int n_in,
                              void* d_out, int out_size) {
    (void)in_sizes; (void)n_in; (void)out_size;
    const int SMEM_BYTES = (576 * 16 + 16 * 576 + 128 * 16 + 2 * 512 + 64
                            + 2 * 128 * RS) * 4;
    cudaFuncSetAttribute(cfc_kernel, cudaFuncAttributeMaxDynamicSharedMemorySize, SMEM_BYTES);
    cfc_kernel<<<NCTA, NTHR, SMEM_BYTES>>>(
        (const float*)d_in[0],  (const float*)d_in[1],  (const float*)d_in[2],
        (const float*)d_in[3],  (const float*)d_in[4],  (const float*)d_in[5],
        (const float*)d_in[6],  (const float*)d_in[7],  (const float*)d_in[8],
        (const float*)d_in[9],  (const float*)d_in[10], (const float*)d_in[11],
        (const float*)d_in[12], (const float*)d_in[13], (const float*)d_in[14],
        (const float*)d_in[15], (float*)d_out);
}

// round 9
// speedup vs baseline: 1.8440x; 1.1536x over previous
#include <cuda_runtime.h>

// Problem shape (fixed by reference)
#define Bdim  128
#define Tdim  1024
#define Idim  64
#define Hdim  512
#define BBdim 128
#define Odim  2

#define NCTA 128   // one CTA per 4 hidden units; also CTA j <-> batch j for phys head
#define NTHR 512   // 16 warps

#define RS    68   // buffer row stride in floats (17 float4s -> conflict-free LDS.128)
#define PSTR  2176 // 128*17, partial-reduction block stride (8 blocks fill buf0+buf1)

// Cross-CTA state (persistent kernel; no allocations allowed)
__device__ float g_h[Bdim * Hdim];      // h_{t-1} / h_t
__device__ float g_hl[Bdim * Hdim];     // h_lstm at current step
__device__ float g_f[Bdim * BBdim];     // backbone activations
__device__ unsigned g_bar_count;
__device__ volatile unsigned g_bar_flag;

__device__ __forceinline__ float sigm(float v) { return 1.0f / (1.0f + expf(-v)); }

// Proven atomic barrier, split into arrive / wait (R8).
__device__ __forceinline__ void bar_arrive(unsigned &expect) {
    __syncthreads();
    expect += 1u;
    if (threadIdx.x == 0) {
        __threadfence();
        if (atomicAdd(&g_bar_count, 1u) == NCTA - 1) {
            g_bar_count = 0;
            __threadfence();
            g_bar_flag = expect;
        }
    }
}
__device__ __forceinline__ void bar_wait(unsigned expect) {
    if (threadIdx.x == 0) {
        while (g_bar_flag != expect) { }
    }
    __syncthreads();
}

// 16 gate-FMAs for TWO batches against one weight row: 4 LDS.128 + 16 FFMA2.
// Each weight load now feeds 2 batches (batch-blocked -> half the weight LDS).
__device__ __forceinline__ void fma16x2_dual(unsigned long long aL[8],
                                             unsigned long long aH[8],
                                             const float* wrow, float vL, float vH) {
    unsigned long long vL2, vH2;
    asm("mov.b64 %0, {%1, %1};" : "=l"(vL2) : "r"(__float_as_uint(vL)));
    asm("mov.b64 %0, {%1, %1};" : "=l"(vH2) : "r"(__float_as_uint(vH)));
    #pragma unroll
    for (int g = 0; g < 4; ++g) {
        ulonglong2 w2 = *(const ulonglong2*)(wrow + g * 4);
        asm("fma.rn.f32x2 %0, %1, %2, %0;" : "+l"(aL[2*g])   : "l"(w2.x), "l"(vL2));
        asm("fma.rn.f32x2 %0, %1, %2, %0;" : "+l"(aH[2*g])   : "l"(w2.x), "l"(vH2));
        asm("fma.rn.f32x2 %0, %1, %2, %0;" : "+l"(aL[2*g+1]) : "l"(w2.y), "l"(vL2));
        asm("fma.rn.f32x2 %0, %1, %2, %0;" : "+l"(aH[2*g+1]) : "l"(w2.y), "l"(vH2));
    }
}

// One 4-k slab (one float4 of activations per batch) of the gate GEMM.
__device__ __forceinline__ void gemmA_4k(unsigned long long aL[8],
                                         unsigned long long aH[8],
                                         const float* rl, const float* rh,
                                         const float* wpc) {
    float4 al = *(const float4*)rl;
    float4 ah = *(const float4*)rh;
    fma16x2_dual(aL, aH, wpc +  0, al.x, ah.x);
    fma16x2_dual(aL, aH, wpc + 16, al.y, ah.y);
    fma16x2_dual(aL, aH, wpc + 32, al.z, ah.z);
    fma16x2_dual(aL, aH, wpc + 48, al.w, ah.w);
}

__device__ __forceinline__ float pk_lo(unsigned long long p) {
    return __uint_as_float((unsigned)(p & 0xffffffffu));
}
__device__ __forceinline__ float pk_hi(unsigned long long p) {
    return __uint_as_float((unsigned)(p >> 32));
}

__global__ __launch_bounds__(NTHR, 1)
void cfc_kernel(const float* __restrict__ x,
                const float* __restrict__ lstm_Wi, const float* __restrict__ lstm_bi,
                const float* __restrict__ lstm_Wh,
                const float* __restrict__ bb_W,  const float* __restrict__ bb_b,
                const float* __restrict__ ff1_W, const float* __restrict__ ff1_b,
                const float* __restrict__ ff2_W, const float* __restrict__ ff2_b,
                const float* __restrict__ ta_W,  const float* __restrict__ ta_b,
                const float* __restrict__ tb_W,  const float* __restrict__ tb_b,
                const float* __restrict__ head_W, const float* __restrict__ head_b,
                float* __restrict__ out)
{
    extern __shared__ float sm[];
    float* wA2  = sm;                    // [576][16] gate weights, k-major layout
    float* wB   = wA2 + 576 * 16;        // [16][576] bb_W row block (row-major)
    float* wC2  = wB + 16 * 576;         // [128][16] ff1/ff2/ta/tb, k-major
    float* hW   = wC2 + 128 * 16;        // [2][512] head
    float* bA   = hW + 2 * 512;          // 16
    float* bB   = bA + 16;               // 16
    float* bC   = bB + 16;               // 16
    float* hb   = bC + 16;               // 16 (2 used)
    float* buf0 = hb + 16;               // [128][RS] streaming tile
    float* buf1 = buf0 + 128 * RS;       // [128][RS]; buf0..buf1 = 17408 floats,
                                         // also 8 partial blocks of PSTR exactly

    const int tid = threadIdx.x;
    const int j   = blockIdx.x;          // owns hidden units 4j..4j+3; batch j for head
    const int b2  = tid & 63;            // batch pair: handles b2 and b2+64
    const int oct = tid >> 6;            // k-split 0..7 (uniform per warp)
    const int blo = b2, bhi = b2 + 64;
    const int bb0 = (j >> 3) * 8;        // phase-B batch block
    const int jj0 = (j & 7) * 16;        // phase-B bb_W row block

    // ---- One-time: resident weights into smem ----
    for (int idx = tid; idx < 576 * 16; idx += NTHR) {
        int k = idx >> 4, q = idx & 15;
        int grow = (q >> 2) * Hdim + 4 * j + (q & 3);   // gate g=q>>2, unit u=q&3
        wA2[idx] = (k < Idim) ? lstm_Wi[grow * Idim + k]
                              : lstm_Wh[grow * Hdim + (k - Idim)];
    }
    for (int idx = tid; idx < 16 * 576; idx += NTHR) {
        int r = idx / 576, k = idx - r * 576;
        wB[idx] = bb_W[(jj0 + r) * 576 + k];
    }
    for (int idx = tid; idx < 128 * 16; idx += NTHR) {
        int k = idx >> 4, r = idx & 15;
        const float* Wm = (r < 4) ? ff1_W : (r < 8) ? ff2_W : (r < 12) ? ta_W : tb_W;
        wC2[idx] = Wm[(4 * j + (r & 3)) * BBdim + k];
    }
    for (int idx = tid; idx < 2 * Hdim; idx += NTHR) hW[idx] = head_W[idx];
    if (tid < 16) {
        bA[tid] = lstm_bi[(tid >> 2) * Hdim + 4 * j + (tid & 3)];
        bB[tid] = bb_b[jj0 + tid];
        const float* bm = (tid < 4) ? ff1_b : (tid < 8) ? ff2_b : (tid < 12) ? ta_b : tb_b;
        bC[tid] = bm[4 * j + (tid & 3)];
    }
    if (tid < 2) hb[tid] = head_b[tid];
    __syncthreads();

    unsigned expect = 0;
    if (tid == 0) expect = g_bar_flag;   // race-free epoch base

    float cReg[4] = {0.f, 0.f, 0.f, 0.f};  // cell state for batch==tid (tid<128)

    for (int t = 0; t < Tdim; ++t) {
        // ============ Phase A: z = [x_t,h] @ W.T, LSTM update ============
        unsigned long long aLo[8], aHi[8];
        #pragma unroll
        for (int p = 0; p < 8; p++) { aLo[p] = 0ull; aHi[p] = 0ull; }

        // --- bar3(t-1) overlap window: stage x chunk 0, compute its 1st half ---
        {
            float4 st[4];
            #pragma unroll
            for (int r4 = 0; r4 < 4; r4++) {
                int idx4 = tid + NTHR * r4;
                int row = idx4 >> 4, c4 = idx4 & 15;
                st[r4] = *(const float4*)(x + (long)row * (Tdim * Idim) + t * Idim + c4 * 4);
            }
            #pragma unroll
            for (int r4 = 0; r4 < 4; r4++) {
                int idx4 = tid + NTHR * r4;
                int row = idx4 >> 4, c4 = idx4 & 15;
                *(float4*)(buf0 + row * RS + c4 * 4) = st[r4];
            }
        }
        __syncthreads();
        gemmA_4k(aLo, aHi, buf0 + blo * RS + oct * 8, buf0 + bhi * RS + oct * 8,
                 wA2 + (oct * 8) * 16);

        bar_wait(expect);    // bar3(t-1): h_{t-1} ready (no-op at t=0)

        if (t > 0) {
            float4 st[4];
            // prefetch h chunk 1 (g_h cols 0..63) while finishing chunk 0
            #pragma unroll
            for (int r4 = 0; r4 < 4; r4++) {
                int idx4 = tid + NTHR * r4;
                int row = idx4 >> 4, c4 = idx4 & 15;
                st[r4] = __ldcg((const float4*)(g_h + row * Hdim + c4 * 4));
            }
            gemmA_4k(aLo, aHi, buf0 + blo * RS + oct * 8 + 4, buf0 + bhi * RS + oct * 8 + 4,
                     wA2 + (oct * 8 + 4) * 16);
            #pragma unroll
            for (int r4 = 0; r4 < 4; r4++) {
                int idx4 = tid + NTHR * r4;
                int row = idx4 >> 4, c4 = idx4 & 15;
                *(float4*)(buf1 + row * RS + c4 * 4) = st[r4];
            }
            __syncthreads();

            for (int c = 1; c < 9; ++c) {
                float4 st2[4];
                if (c < 8) {             // prefetch next h chunk (g_h cols c*64..)
                    #pragma unroll
                    for (int r4 = 0; r4 < 4; r4++) {
                        int idx4 = tid + NTHR * r4;
                        int row = idx4 >> 4, c4 = idx4 & 15;
                        st2[r4] = __ldcg((const float4*)(g_h + row * Hdim + c * 64 + c4 * 4));
                    }
                }
                {
                    const float* cb = (c & 1) ? buf1 : buf0;
                    const float* rl = cb + blo * RS + oct * 8;
                    const float* rh = cb + bhi * RS + oct * 8;
                    const float* wpc = wA2 + (c * 64 + oct * 8) * 16;
                    gemmA_4k(aLo, aHi, rl, rh, wpc);
                    gemmA_4k(aLo, aHi, rl + 4, rh + 4, wpc + 64);
                }
                if (c < 8) {
                    float* nb = ((c + 1) & 1) ? buf1 : buf0;
                    #pragma unroll
                    for (int r4 = 0; r4 < 4; r4++) {
                        int idx4 = tid + NTHR * r4;
                        int row = idx4 >> 4, c4 = idx4 & 15;
                        *(float4*)(nb + row * RS + c4 * 4) = st2[r4];
                    }
                }
                __syncthreads();
            }
        } else {
            gemmA_4k(aLo, aHi, buf0 + blo * RS + oct * 8 + 4, buf0 + bhi * RS + oct * 8 + 4,
                     wA2 + (oct * 8 + 4) * 16);
            __syncthreads();             // protect buf0 before partial writes
        }

        // 8-way k-partial dump: all threads write both batches' partials
        {
            float* dl = buf0 + oct * PSTR + blo * 17;
            float* dh = buf0 + oct * PSTR + bhi * 17;
            #pragma unroll
            for (int p = 0; p < 8; p++) {
                dl[2*p] = pk_lo(aLo[p]); dl[2*p+1] = pk_hi(aLo[p]);
                dh[2*p] = pk_lo(aHi[p]); dh[2*p+1] = pk_hi(aHi[p]);
            }
        }
        __syncthreads();
        if (tid < 128) {                 // thread tid finalizes batch tid
            int b = tid;
            float z[16];
            #pragma unroll
            for (int q = 0; q < 16; q++) z[q] = bA[q];
            #pragma unroll
            for (int p = 0; p < 8; p++) {
                const float* s = buf0 + p * PSTR + b * 17;
                #pragma unroll
                for (int q = 0; q < 16; q++) z[q] += s[q];
            }
            float hl[4];
            #pragma unroll
            for (int u = 0; u < 4; u++) {
                // z rows: [0..3]=i_, [4..7]=ig, [8..11]=fg, [12..15]=og
                float cn = cReg[u] * sigm(z[8 + u] + 1.0f) + tanhf(z[u]) * sigm(z[4 + u]);
                cReg[u] = cn;
                hl[u] = tanhf(cn) * sigm(z[12 + u]);
            }
            *(float4*)(g_hl + b * Hdim + 4 * j) = make_float4(hl[0], hl[1], hl[2], hl[3]);
        }

        bar_arrive(expect);  // bar1: h_lstm posted

        // --- bar1 overlap window: phys head (t-1) + Phase-B x staging ---
        if (t > 0 && tid < 64) {
            int o = tid >> 5, l = tid & 31;
            float s = 0.f;
            for (int n = l; n < Hdim; n += 32)
                s += __ldcg(g_h + j * Hdim + n) * hW[o * Hdim + n];
            #pragma unroll
            for (int off = 16; off; off >>= 1) s += __shfl_down_sync(0xffffffffu, s, off);
            if (l == 0) out[((long)j * Tdim + (t - 1)) * Odim + o] = s + hb[o];
        }
        if (tid >= 128 && tid < 256) {   // B rows' x columns (no h_lstm dependency)
            int idx = tid - 128;
            int row = idx >> 4, col = (idx & 15) * 4;
            *(float4*)(buf0 + row * 576 + col) =
                *(const float4*)(x + (long)(bb0 + row) * (Tdim * Idim) + t * Idim + col);
        }

        bar_wait(expect);    // bar1: h_lstm ready

        // ============ Phase B: f = lecun_tanh([x_t,h_lstm] @ bbW.T + b) ============
        #pragma unroll
        for (int r2 = 0; r2 < 2; ++r2) {     // stage h_lstm columns (8 rows x 512 cols)
            int idx4 = tid + NTHR * r2;
            int row = idx4 >> 7, c4 = idx4 & 127;
            int col = 64 + c4 * 4;
            *(float4*)(buf0 + row * 576 + col) =
                __ldcg((const float4*)(g_hl + (bb0 + row) * Hdim + col - 64));
        }
        __syncthreads();
        {
            int w  = tid >> 5, l = tid & 31;
            int lb = w >> 1, kh = w & 1;     // local batch 0..7, k-half 0/1
            float a[16];
            #pragma unroll
            for (int r = 0; r < 16; r++) a[r] = 0.f;
            const float* xr = buf0 + lb * 576 + kh * 288;
            const float* wb = wB + kh * 288;
            for (int it = 0; it < 9; ++it) {
                int kk = it * 32 + l;
                float v = xr[kk];
                #pragma unroll
                for (int r = 0; r < 16; r++) a[r] = fmaf(v, wb[r * 576 + kk], a[r]);
            }
            #pragma unroll
            for (int r = 0; r < 16; r++) {
                #pragma unroll
                for (int off = 16; off; off >>= 1)
                    a[r] += __shfl_down_sync(0xffffffffu, a[r], off);
            }
            if (l == 0) {
                #pragma unroll
                for (int r = 0; r < 16; r++) buf1[(lb * 2 + kh) * 16 + r] = a[r];
            }
        }
        __syncthreads();
        if (tid < 128) {
            int lb = tid >> 4, r = tid & 15;
            float v = buf1[lb * 32 + r] + buf1[lb * 32 + 16 + r] + bB[r];
            g_f[(bb0 + lb) * BBdim + jj0 + r] = 1.7159f * tanhf(0.666f * v);
        }

        bar_arrive(expect);  // bar2: f posted
        bar_wait(expect);    // bar2: f ready

        // ============ Phase C: ff1/ff2/ta/tb, h_new ============
        #pragma unroll
        for (int r8 = 0; r8 < 8; ++r8) {     // stage full f (128x128) into buf0|buf1
            int idx4 = tid + NTHR * r8;
            int row = idx4 >> 5, c4 = idx4 & 31;
            float4 v = __ldcg((const float4*)(g_f + row * BBdim + c4 * 4));
            *(float4*)(((c4 < 16) ? buf0 : buf1) + row * RS + (c4 & 15) * 4) = v;
        }
        __syncthreads();
        unsigned long long cLo[8], cHi[8];
        #pragma unroll
        for (int p = 0; p < 8; p++) { cLo[p] = 0ull; cHi[p] = 0ull; }
        {
            const float* base = (oct >= 4) ? buf1 : buf0;
            const int coff = (oct & 3) * 16;
            const float* rl = base + blo * RS + coff;
            const float* rh = base + bhi * RS + coff;
            const float* wpc = wC2 + (oct * 16) * 16;
            #pragma unroll
            for (int k4 = 0; k4 < 4; ++k4)
                gemmA_4k(cLo, cHi, rl + k4 * 4, rh + k4 * 4, wpc + k4 * 64);
        }
        __syncthreads();
        {
            float* dl = buf0 + oct * PSTR + blo * 17;
            float* dh = buf0 + oct * PSTR + bhi * 17;
            #pragma unroll
            for (int p = 0; p < 8; p++) {
                dl[2*p] = pk_lo(cLo[p]); dl[2*p+1] = pk_hi(cLo[p]);
                dh[2*p] = pk_lo(cHi[p]); dh[2*p+1] = pk_hi(cHi[p]);
            }
        }
        __syncthreads();
        if (tid < 128) {
            int b = tid;
            float z[16];
            #pragma unroll
            for (int r = 0; r < 16; r++) z[r] = bC[r];
            #pragma unroll
            for (int p = 0; p < 8; p++) {
                const float* s = buf0 + p * PSTR + b * 17;
                #pragma unroll
                for (int r = 0; r < 16; r++) z[r] += s[r];
            }
            float hn[4];
            #pragma unroll
            for (int u = 0; u < 4; u++) {
                float f1 = tanhf(z[u]);                  // ff1
                float f2 = tanhf(z[4 + u]);              // ff2
                float ti = sigm(z[8 + u] + z[12 + u]);   // sigmoid(ta*1 + tb)
                hn[u] = f1 * (1.f - ti) + ti * f2;
            }
            *(float4*)(g_h + b * Hdim + 4 * j) = make_float4(hn[0], hn[1], hn[2], hn[3]);
        }

        bar_arrive(expect);  // bar3: h_t posted (waited at top of next iteration)
    }

    bar_wait(expect);        // final bar3: h_{T-1} ready everywhere

    // ---- Epilogue: phys for t = T-1, and last_h ----
    if (tid < 64) {
        int o = tid >> 5, l = tid & 31;
        float s = 0.f;
        for (int n = l; n < Hdim; n += 32)
            s += __ldcg(g_h + j * Hdim + n) * hW[o * Hdim + n];
        #pragma unroll
        for (int off = 16; off; off >>= 1) s += __shfl_down_sync(0xffffffffu, s, off);
        if (l == 0) out[((long)j * Tdim + (Tdim - 1)) * Odim + o] = s + hb[o];
    }
    float* out_lh = out + (long)Bdim * Tdim * Odim;
    for (int i4 = tid; i4 < Hdim / 4; i4 += NTHR) {
        float4 v = __ldcg((const float4*)(g_h + j * Hdim + i4 * 4));
        *(float4*)(out_lh + j * Hdim + i4 * 4) = v;
    }
}

extern "C" void kernel_launch(void* const* d_in, const int* in_sizes, int n_in,
                              void* d_out, int out_size) {
    (void)in_sizes; (void)n_in; (void)out_size;
    const int SMEM_BYTES = (576 * 16 + 16 * 576 + 128 * 16 + 2 * 512 + 64
                            + 2 * 128 * RS) * 4;
    cudaFuncSetAttribute(cfc_kernel, cudaFuncAttributeMaxDynamicSharedMemorySize, SMEM_BYTES);
    cfc_kernel<<<NCTA, NTHR, SMEM_BYTES>>>(
        (const float*)d_in[0],  (const float*)d_in[1],  (const float*)d_in[2],
        (const float*)d_in[3],  (const float*)d_in[4],  (const float*)d_in[5],
        (const float*)d_in[6],  (const float*)d_in[7],  (const float*)d_in[8],
        (const float*)d_in[9],  (const float*)d_in[10], (const float*)d_in[11],
        (const float*)d_in[12], (const float*)d_in[13], (const float*)d_in[14],
        (const float*)d_in[15], (float*)d_out);
}